// round 5
// baseline (speedup 1.0000x reference)
#include <cuda_runtime.h>
#include <cstdint>

#define BSZ  256
#define TSEQ 512
#define HIDN 256

typedef unsigned long long ull;

// ---- static scratch ----
__device__ float g_xg[(size_t)TSEQ * BSZ * 1024];
__device__ float g_hist0[(size_t)TSEQ * BSZ * HIDN];
__device__ float g_hist1[(size_t)TSEQ * BSZ * HIDN];
__device__ unsigned g_bar[128];   // [batch-group][producer ni] per-warp release counters

__global__ void reset_bar() { if (threadIdx.x < 128) g_bar[threadIdx.x] = 0u; }

__device__ __forceinline__ float sigm(float x) { return 1.f / (1.f + __expf(-x)); }
__device__ __forceinline__ float ftanh(float x) {
    float e = __expf(-2.f * fabsf(x));
    return copysignf((1.f - e) / (1.f + e), x);
}

// ---- packed fp32x2 (Blackwell FFMA2) ----
__device__ __forceinline__ ull ffma2(ull a, ull b, ull c) {
    ull d; asm("fma.rn.f32x2 %0, %1, %2, %3;" : "=l"(d) : "l"(a), "l"(b), "l"(c)); return d;
}
__device__ __forceinline__ ull dup2(float x) {
    ull r; asm("mov.b64 %0, {%1, %1};" : "=l"(r) : "f"(x)); return r;
}
__device__ __forceinline__ float2 unpk(ull v) {
    float2 f; asm("mov.b64 {%0, %1}, %2;" : "=f"(f.x), "=f"(f.y) : "l"(v)); return f;
}

// ---- scoped sync primitives ----
__device__ __forceinline__ unsigned ld_acq(const unsigned* p) {
    unsigned v; asm volatile("ld.acquire.gpu.global.b32 %0, [%1];" : "=r"(v) : "l"(p)); return v;
}
__device__ __forceinline__ void red_rel_add(unsigned* p, unsigned v) {
    asm volatile("red.release.gpu.global.add.u32 [%0], %1;" :: "l"(p), "r"(v) : "memory");
}

// ---- GEMM with register-prefetch double buffering ----
template<int K, bool XMODE>
__global__ void __launch_bounds__(256, 2) gemm_xg(
    const float* __restrict__ A, const float* __restrict__ W,
    const float* __restrict__ b1, const float* __restrict__ b2,
    float* __restrict__ out)
{
    __shared__ float As[16][132];
    __shared__ float Ws[16][132];
    const int m0 = blockIdx.x * 128, n0 = blockIdx.y * 128;
    const int tid = threadIdx.x;
    const int tm = tid >> 4, tn = tid & 15;

    // per-thread staging coords
    int rrv[2], kqv[2];
#pragma unroll
    for (int i = 0; i < 2; i++) { int idx = tid + (i << 8); rrv[i] = idx >> 2; kqv[i] = (idx & 3) << 2; }
    size_t aoffv[2];
#pragma unroll
    for (int i = 0; i < 2; i++) {
        int row = m0 + rrv[i];
        if (XMODE) aoffv[i] = ((size_t)(row & 255) * TSEQ + (row >> 8)) * K;
        else       aoffv[i] = (size_t)row * K;
    }

    ull acc[8][4];
#pragma unroll
    for (int i = 0; i < 8; i++)
#pragma unroll
        for (int j = 0; j < 4; j++) acc[i][j] = 0ull;

    float4 pa[2], pw[2];
#pragma unroll
    for (int i = 0; i < 2; i++) {
        pa[i] = *reinterpret_cast<const float4*>(A + aoffv[i] + kqv[i]);
        pw[i] = *reinterpret_cast<const float4*>(W + (size_t)(n0 + rrv[i]) * K + kqv[i]);
    }

    for (int kt = 0; kt < K; kt += 16) {
#pragma unroll
        for (int i = 0; i < 2; i++) {
            int k = kqv[i], rr = rrv[i];
            As[k+0][rr]=pa[i].x; As[k+1][rr]=pa[i].y; As[k+2][rr]=pa[i].z; As[k+3][rr]=pa[i].w;
            Ws[k+0][rr]=pw[i].x; Ws[k+1][rr]=pw[i].y; Ws[k+2][rr]=pw[i].z; Ws[k+3][rr]=pw[i].w;
        }
        __syncthreads();
        if (kt + 16 < K) {
#pragma unroll
            for (int i = 0; i < 2; i++) {
                pa[i] = *reinterpret_cast<const float4*>(A + aoffv[i] + kt + 16 + kqv[i]);
                pw[i] = *reinterpret_cast<const float4*>(W + (size_t)(n0 + rrv[i]) * K + kt + 16 + kqv[i]);
            }
        }
#pragma unroll
        for (int k = 0; k < 16; k++) {
            float a[8];
            *reinterpret_cast<float4*>(&a[0]) = *reinterpret_cast<const float4*>(&As[k][tm << 3]);
            *reinterpret_cast<float4*>(&a[4]) = *reinterpret_cast<const float4*>(&As[k][(tm << 3) + 4]);
            ulonglong2 wa = *reinterpret_cast<const ulonglong2*>(&Ws[k][tn << 3]);
            ulonglong2 wb = *reinterpret_cast<const ulonglong2*>(&Ws[k][(tn << 3) + 4]);
            ull w2[4] = {wa.x, wa.y, wb.x, wb.y};
#pragma unroll
            for (int i = 0; i < 8; i++) {
                ull ad = dup2(a[i]);
#pragma unroll
                for (int j = 0; j < 4; j++) acc[i][j] = ffma2(ad, w2[j], acc[i][j]);
            }
        }
        __syncthreads();
    }

    float bv[8];
#pragma unroll
    for (int j = 0; j < 8; j++) bv[j] = b1[n0 + (tn << 3) + j] + b2[n0 + (tn << 3) + j];
#pragma unroll
    for (int i = 0; i < 8; i++) {
        size_t ro = (size_t)(m0 + (tm << 3) + i) * 1024 + n0 + (tn << 3);
        float2 p0 = unpk(acc[i][0]), p1 = unpk(acc[i][1]);
        float2 p2 = unpk(acc[i][2]), p3 = unpk(acc[i][3]);
        *reinterpret_cast<float4*>(out + ro)     = make_float4(p0.x+bv[0], p0.y+bv[1], p1.x+bv[2], p1.y+bv[3]);
        *reinterpret_cast<float4*>(out + ro + 4) = make_float4(p2.x+bv[4], p2.y+bv[5], p3.x+bv[6], p3.y+bv[7]);
    }
}

// ---- persistent LSTM recurrence: 128 CTAs = 16 batch-groups x 8 n-groups ----
// Per-producer decoupled waits: kg group (64 threads) depends only on producers {2kg, 2kg+1}.
__global__ void __launch_bounds__(256, 1) rec_kernel(
    const float* __restrict__ xg, const float* __restrict__ Whh,
    float* __restrict__ hist)
{
    extern __shared__ float sm[];
    float* Wsh = sm;            // 32768 floats
    float* hsh = Wsh + 32768;   // 16 x 520 dup-h = 8320
    float* red = hsh + 8320;    // 4 x 16 x 128   = 8192

    const int bi = blockIdx.x >> 3, ni = blockIdx.x & 7;
    const int b0 = bi << 4, n0 = ni << 5;
    const int tid = threadIdx.x;
    const int lane = tid & 31;
    const int kg = tid >> 6, cid = tid & 63;
    const int bb0 = (cid >> 4) << 2;
    const int c0  = (cid & 15) << 3;
    // staging coords within kg group: sb = batch 0..15, sk4 = k offset {0,16,32,48}
    const int sb  = cid >> 2;
    const int sk4 = (cid & 3) << 4;

    for (int idx = tid; idx < 8192; idx += 256) {
        int kq = idx & 63, c = idx >> 6;
        int g = c >> 5, nn = c & 31;
        float4 v = *reinterpret_cast<const float4*>(
            Whh + (size_t)((g << 8) + n0 + nn) * HIDN + (kq << 2));
        int k = kq << 2;
        Wsh[(k+0)*128+c]=v.x; Wsh[(k+1)*128+c]=v.y; Wsh[(k+2)*128+c]=v.z; Wsh[(k+3)*128+c]=v.w;
    }
    __syncthreads();

    const int p0i = tid << 1;
    const int eb0 = p0i >> 5,      enn0 = p0i & 31;
    const int eb1 = (p0i+1) >> 5,  enn1 = (p0i+1) & 31;

    unsigned* cnt0 = g_bar + (bi << 3) + (kg << 1);
    unsigned* cnt1 = cnt0 + 1;
    unsigned* mycnt = g_bar + (bi << 3) + ni;

    float creg[2] = {0.f, 0.f};

    for (int t = 0; t < TSEQ; t++) {
        // prefetch gate preactivations (independent of h)
        const float* xgp = xg + ((size_t)t * BSZ + b0) * 1024;
        float xv0[4], xv1[4];
#pragma unroll
        for (int g = 0; g < 4; g++) {
            xv0[g] = __ldg(xgp + (eb0 << 10) + (g << 8) + n0 + enn0);
            xv1[g] = __ldg(xgp + (eb1 << 10) + (g << 8) + n0 + enn1);
        }

        ull acc2[4][4];
#pragma unroll
        for (int i = 0; i < 4; i++)
#pragma unroll
            for (int j = 0; j < 4; j++) acc2[i][j] = 0ull;

        if (t > 0) {
            // wait ONLY on this kg's two producers (8 warp-arrivals each per step)
            const unsigned tgt = (unsigned)(t << 3);
            while (ld_acq(cnt0) < tgt) {}
            while (ld_acq(cnt1) < tgt) {}

            // stage own 64-k slice of h(t-1), duplicated pairs
            const float* hp = hist + ((size_t)(t - 1) * BSZ + b0 + sb) * HIDN + (kg << 6) + sk4;
            float* dst = hsh + sb * 520 + (((kg << 6) + sk4) << 1);
#pragma unroll
            for (int i = 0; i < 4; i++) {
                float4 v = *reinterpret_cast<const float4*>(hp + (i << 2));
                *reinterpret_cast<float4*>(dst + (i << 3))     = make_float4(v.x, v.x, v.y, v.y);
                *reinterpret_cast<float4*>(dst + (i << 3) + 4) = make_float4(v.z, v.z, v.w, v.w);
            }
            // kg-group barrier (2 warps, 64 threads)
            asm volatile("bar.sync %0, 64;" :: "r"(kg + 1) : "memory");

            const float* hpL = hsh + bb0 * 520 + (kg << 7);
            const float* wp  = Wsh + ((kg << 6) * 128) + c0;
#pragma unroll 8
            for (int k = 0; k < 64; k++) {
                ull hd0 = *reinterpret_cast<const ull*>(hpL + (k << 1));
                ull hd1 = *reinterpret_cast<const ull*>(hpL +  520 + (k << 1));
                ull hd2 = *reinterpret_cast<const ull*>(hpL + 1040 + (k << 1));
                ull hd3 = *reinterpret_cast<const ull*>(hpL + 1560 + (k << 1));
                ulonglong2 wa = *reinterpret_cast<const ulonglong2*>(wp);
                ulonglong2 wb = *reinterpret_cast<const ulonglong2*>(wp + 4);
                wp += 128;
                ull w2[4] = {wa.x, wa.y, wb.x, wb.y};
#pragma unroll
                for (int j = 0; j < 4; j++) {
                    acc2[0][j] = ffma2(hd0, w2[j], acc2[0][j]);
                    acc2[1][j] = ffma2(hd1, w2[j], acc2[1][j]);
                    acc2[2][j] = ffma2(hd2, w2[j], acc2[2][j]);
                    acc2[3][j] = ffma2(hd3, w2[j], acc2[3][j]);
                }
            }
        }

        // k-split partials
#pragma unroll
        for (int i = 0; i < 4; i++) {
            float* rp = red + (kg << 11) + (bb0 + i) * 128 + c0;
            *reinterpret_cast<ulonglong2*>(rp)     = make_ulonglong2(acc2[i][0], acc2[i][1]);
            *reinterpret_cast<ulonglong2*>(rp + 4) = make_ulonglong2(acc2[i][2], acc2[i][3]);
        }
        __syncthreads();

        // epilogue (c in registers), then per-warp release
        float* ho = hist + ((size_t)t * BSZ + b0) * HIDN;
        {
            int cb = eb0 * 128 + enn0;
            float gv[4];
#pragma unroll
            for (int g = 0; g < 4; g++) {
                int c = cb + (g << 5);
                gv[g] = red[c] + red[c + 2048] + red[c + 4096] + red[c + 6144] + xv0[g];
            }
            float cn = sigm(gv[1]) * creg[0] + sigm(gv[0]) * ftanh(gv[2]);
            creg[0] = cn;
            ho[(eb0 << 8) + n0 + enn0] = sigm(gv[3]) * ftanh(cn);
        }
        {
            int cb = eb1 * 128 + enn1;
            float gv[4];
#pragma unroll
            for (int g = 0; g < 4; g++) {
                int c = cb + (g << 5);
                gv[g] = red[c] + red[c + 2048] + red[c + 4096] + red[c + 6144] + xv1[g];
            }
            float cn = sigm(gv[1]) * creg[1] + sigm(gv[0]) * ftanh(gv[2]);
            creg[1] = cn;
            ho[(eb1 << 8) + n0 + enn1] = sigm(gv[3]) * ftanh(cn);
        }
        if (lane == 0) red_rel_add(mycnt, 1u);   // warp's h stores published
        __syncthreads();                          // protect red/hsh for next step
    }
}

// ---- head ----
__global__ void head_kernel(const float* __restrict__ Wh, const float* __restrict__ bh,
                            float* __restrict__ out)
{
    __shared__ float rs[8];
    int b = blockIdx.x, tid = threadIdx.x;
    float v = g_hist1[((size_t)(TSEQ - 1) * BSZ + b) * HIDN + tid] * Wh[tid];
#pragma unroll
    for (int o = 16; o > 0; o >>= 1) v += __shfl_down_sync(0xffffffffu, v, o);
    if ((tid & 31) == 0) rs[tid >> 5] = v;
    __syncthreads();
    if (tid < 8) {
        float s = rs[tid];
#pragma unroll
        for (int o = 4; o > 0; o >>= 1) s += __shfl_down_sync(0xffu, s, o);
        if (tid == 0) out[b] = s + bh[0];
    }
}

extern "C" void kernel_launch(void* const* d_in, const int* in_sizes, int n_in,
                              void* d_out, int out_size)
{
    const float* x      = (const float*)d_in[0];
    const float* W_ih0  = (const float*)d_in[1];
    const float* W_hh0  = (const float*)d_in[2];
    const float* b_ih0  = (const float*)d_in[3];
    const float* b_hh0  = (const float*)d_in[4];
    const float* W_ih1  = (const float*)d_in[5];
    const float* W_hh1  = (const float*)d_in[6];
    const float* b_ih1  = (const float*)d_in[7];
    const float* b_hh1  = (const float*)d_in[8];
    const float* W_head = (const float*)d_in[9];
    const float* b_head = (const float*)d_in[10];
    float* out = (float*)d_out;

    void *pxg, *ph0, *ph1;
    cudaGetSymbolAddress(&pxg, g_xg);
    cudaGetSymbolAddress(&ph0, g_hist0);
    cudaGetSymbolAddress(&ph1, g_hist1);
    float* xg = (float*)pxg; float* h0 = (float*)ph0; float* h1 = (float*)ph1;

    const int SMEM = 49280 * 4;   // 197120 B
    cudaFuncSetAttribute(rec_kernel, cudaFuncAttributeMaxDynamicSharedMemorySize, SMEM);

    dim3 gg(1024, 8);
    gemm_xg<64,  true ><<<gg, 256>>>(x,  W_ih0, b_ih0, b_hh0, xg);
    reset_bar<<<1, 128>>>();
    rec_kernel<<<128, 256, SMEM>>>(xg, W_hh0, h0);
    gemm_xg<256, false><<<gg, 256>>>(h0, W_ih1, b_ih1, b_hh1, xg);
    reset_bar<<<1, 128>>>();
    rec_kernel<<<128, 256, SMEM>>>(xg, W_hh1, h1);
    head_kernel<<<256, 256>>>(W_head, b_head, out);
}

// round 6
// speedup vs baseline: 1.4311x; 1.4311x over previous
#include <cuda_runtime.h>
#include <cstdint>

#define BSZ  256
#define TSEQ 512
#define HIDN 256

typedef unsigned long long ull;

// ---- static scratch ----
// xg layout: [t][b][n][4]  (4 gates contiguous per (t,b,n))
__device__ float g_xg[(size_t)TSEQ * BSZ * 1024];
__device__ float g_hist0[(size_t)TSEQ * BSZ * HIDN];
__device__ float g_hist1[(size_t)TSEQ * BSZ * HIDN];
__device__ unsigned g_bar[16];

__global__ void reset_bar() { if (threadIdx.x < 16) g_bar[threadIdx.x] = 0u; }

__device__ __forceinline__ float sigm(float x) { return 1.f / (1.f + __expf(-x)); }
__device__ __forceinline__ float ftanh(float x) {
    float e = __expf(-2.f * fabsf(x));
    return copysignf((1.f - e) / (1.f + e), x);
}

// ---- packed fp32x2 (Blackwell FFMA2) ----
__device__ __forceinline__ ull ffma2(ull a, ull b, ull c) {
    ull d; asm("fma.rn.f32x2 %0, %1, %2, %3;" : "=l"(d) : "l"(a), "l"(b), "l"(c)); return d;
}
__device__ __forceinline__ ull dup2(float x) {
    ull r; asm("mov.b64 %0, {%1, %1};" : "=l"(r) : "f"(x)); return r;
}
__device__ __forceinline__ float2 unpk(ull v) {
    float2 f; asm("mov.b64 {%0, %1}, %2;" : "=f"(f.x), "=f"(f.y) : "l"(v)); return f;
}

// ---- scoped sync ----
__device__ __forceinline__ unsigned ld_acq(const unsigned* p) {
    unsigned v; asm volatile("ld.acquire.gpu.global.b32 %0, [%1];" : "=r"(v) : "l"(p)); return v;
}
__device__ __forceinline__ void red_rel_add(unsigned* p, unsigned v) {
    asm volatile("red.release.gpu.global.add.u32 [%0], %1;" :: "l"(p), "r"(v) : "memory");
}

// ---- GEMM: xg[(m)*256 + n][g] = A_row(m) . W[g*256+n] + b1 + b2 ----
// Block: 128 m x (32 n x 4 gates).  n0 = blockIdx.y*32.  Output gate-interleaved.
template<int K, bool XMODE>
__global__ void __launch_bounds__(256, 2) gemm_xg(
    const float* __restrict__ A, const float* __restrict__ W,
    const float* __restrict__ b1, const float* __restrict__ b2,
    float* __restrict__ out)
{
    __shared__ float As[16][132];
    __shared__ float Ws[16][132];   // c = g*32 + (n-n0)
    const int m0 = blockIdx.x * 128, n0 = blockIdx.y * 32;
    const int tid = threadIdx.x;
    const int tm = tid >> 4, tn = tid & 15;   // 8 m-rows, 2 n-cols x 4 gates

    int rrv[2], kqv[2];
#pragma unroll
    for (int i = 0; i < 2; i++) { int idx = tid + (i << 8); rrv[i] = idx >> 2; kqv[i] = (idx & 3) << 2; }
    size_t aoffv[2], woffv[2];
#pragma unroll
    for (int i = 0; i < 2; i++) {
        int row = m0 + rrv[i];
        if (XMODE) aoffv[i] = ((size_t)(row & 255) * TSEQ + (row >> 8)) * K;
        else       aoffv[i] = (size_t)row * K;
        int wrow = ((rrv[i] >> 5) << 8) + n0 + (rrv[i] & 31);   // gate*256 + n
        woffv[i] = (size_t)wrow * K;
    }

    ull acc[8][4];   // [m-row][gate], pair = (n, n+1)
#pragma unroll
    for (int i = 0; i < 8; i++)
#pragma unroll
        for (int j = 0; j < 4; j++) acc[i][j] = 0ull;

    float4 pa[2], pw[2];
#pragma unroll
    for (int i = 0; i < 2; i++) {
        pa[i] = *reinterpret_cast<const float4*>(A + aoffv[i] + kqv[i]);
        pw[i] = *reinterpret_cast<const float4*>(W + woffv[i] + kqv[i]);
    }

    for (int kt = 0; kt < K; kt += 16) {
#pragma unroll
        for (int i = 0; i < 2; i++) {
            int k = kqv[i], rr = rrv[i];
            As[k+0][rr]=pa[i].x; As[k+1][rr]=pa[i].y; As[k+2][rr]=pa[i].z; As[k+3][rr]=pa[i].w;
            Ws[k+0][rr]=pw[i].x; Ws[k+1][rr]=pw[i].y; Ws[k+2][rr]=pw[i].z; Ws[k+3][rr]=pw[i].w;
        }
        __syncthreads();
        if (kt + 16 < K) {
#pragma unroll
            for (int i = 0; i < 2; i++) {
                pa[i] = *reinterpret_cast<const float4*>(A + aoffv[i] + kt + 16 + kqv[i]);
                pw[i] = *reinterpret_cast<const float4*>(W + woffv[i] + kt + 16 + kqv[i]);
            }
        }
#pragma unroll
        for (int k = 0; k < 16; k++) {
            float a[8];
            *reinterpret_cast<float4*>(&a[0]) = *reinterpret_cast<const float4*>(&As[k][tm << 3]);
            *reinterpret_cast<float4*>(&a[4]) = *reinterpret_cast<const float4*>(&As[k][(tm << 3) + 4]);
            ull w2[4];
#pragma unroll
            for (int g = 0; g < 4; g++)
                w2[g] = *reinterpret_cast<const ull*>(&Ws[k][(g << 5) + (tn << 1)]);
#pragma unroll
            for (int i = 0; i < 8; i++) {
                ull ad = dup2(a[i]);
#pragma unroll
                for (int g = 0; g < 4; g++) acc[i][g] = ffma2(ad, w2[g], acc[i][g]);
            }
        }
        __syncthreads();
    }

    const int n = n0 + (tn << 1);
    float bv0[4], bv1[4];
#pragma unroll
    for (int g = 0; g < 4; g++) {
        bv0[g] = b1[(g << 8) + n]     + b2[(g << 8) + n];
        bv1[g] = b1[(g << 8) + n + 1] + b2[(g << 8) + n + 1];
    }
    float4* out4 = reinterpret_cast<float4*>(out);
#pragma unroll
    for (int i = 0; i < 8; i++) {
        int m = m0 + (tm << 3) + i;
        float2 q0 = unpk(acc[i][0]), q1 = unpk(acc[i][1]);
        float2 q2 = unpk(acc[i][2]), q3 = unpk(acc[i][3]);
        out4[(size_t)m * 256 + n]     = make_float4(q0.x+bv0[0], q1.x+bv0[1], q2.x+bv0[2], q3.x+bv0[3]);
        out4[(size_t)m * 256 + n + 1] = make_float4(q0.y+bv1[0], q1.y+bv1[1], q2.y+bv1[2], q3.y+bv1[3]);
    }
}

// ---- persistent LSTM recurrence: 128 CTAs = 16 batch-groups x 8 n-groups ----
// Dot: 1 warp per 32-k slice (k-split 8), 8 batches x 8 cols per thread.
__global__ void __launch_bounds__(256, 1) rec_kernel(
    const float* __restrict__ xg, const float* __restrict__ Whh,
    float* __restrict__ hist)
{
    extern __shared__ float sm[];
    float* Wsh = sm;            // 32768 floats (k*128 + c), c = g*32+nn
    float* hsh = Wsh + 32768;   // 16 x 260 = 4160
    float* red = hsh + 4160;    // 8 x 16 x 128 = 16384

    const int bi = blockIdx.x >> 3, ni = blockIdx.x & 7;
    const int b0 = bi << 4, n0 = ni << 5;
    const int tid = threadIdx.x;
    const int kg  = tid >> 5;          // warp = k-group (32 k)
    const int cid = tid & 31;
    const int bb  = (cid >> 4) << 3;   // 0 or 8
    const int c0  = (cid & 15) << 3;   // 0..120

    for (int idx = tid; idx < 8192; idx += 256) {
        int kq = idx & 63, c = idx >> 6;
        int g = c >> 5, nn = c & 31;
        float4 v = *reinterpret_cast<const float4*>(
            Whh + (size_t)((g << 8) + n0 + nn) * HIDN + (kq << 2));
        int k = kq << 2;
        Wsh[(k+0)*128+c]=v.x; Wsh[(k+1)*128+c]=v.y; Wsh[(k+2)*128+c]=v.z; Wsh[(k+3)*128+c]=v.w;
    }
    __syncthreads();

    const int p0i = tid << 1;
    const int eb0 = p0i >> 5,      enn0 = p0i & 31;
    const int eb1 = (p0i+1) >> 5,  enn1 = (p0i+1) & 31;

    const float4* xg4 = reinterpret_cast<const float4*>(xg);
    float creg[2] = {0.f, 0.f};

    for (int t = 0; t < TSEQ; t++) {
        // prefetch gate quads (one LDG.128 per cell)
        float4 xv0 = __ldg(&xg4[((size_t)t * BSZ + b0 + eb0) * 256 + n0 + enn0]);
        float4 xv1 = __ldg(&xg4[((size_t)t * BSZ + b0 + eb1) * 256 + n0 + enn1]);

        ull acc2[8][4];
#pragma unroll
        for (int i = 0; i < 8; i++)
#pragma unroll
            for (int j = 0; j < 4; j++) acc2[i][j] = 0ull;

        if (t > 0) {
            const unsigned tgt = (unsigned)(t << 3);
            while (ld_acq(g_bar + bi) < tgt) {}

            // stage h(t-1), un-duplicated
            const float* hp = hist + ((size_t)(t - 1) * BSZ + b0) * HIDN;
#pragma unroll
            for (int i = 0; i < 4; i++) {
                int idx = tid + (i << 8);
                int b = idx >> 6, k4 = (idx & 63) << 2;
                *reinterpret_cast<float4*>(&hsh[b * 260 + k4]) =
                    *reinterpret_cast<const float4*>(hp + (b << 8) + k4);
            }
            __syncthreads();

            const float* hpL = hsh + bb * 260 + (kg << 5);
            const float* wp  = Wsh + ((kg << 5) * 128) + c0;
#pragma unroll 8
            for (int k = 0; k < 32; k++) {
                ulonglong2 wa = *reinterpret_cast<const ulonglong2*>(wp);
                ulonglong2 wb = *reinterpret_cast<const ulonglong2*>(wp + 4);
                wp += 128;
                ull w2[4] = {wa.x, wa.y, wb.x, wb.y};
#pragma unroll
                for (int i = 0; i < 8; i++) {
                    ull hd = dup2(hpL[i * 260 + k]);
                    acc2[i][0] = ffma2(hd, w2[0], acc2[i][0]);
                    acc2[i][1] = ffma2(hd, w2[1], acc2[i][1]);
                    acc2[i][2] = ffma2(hd, w2[2], acc2[i][2]);
                    acc2[i][3] = ffma2(hd, w2[3], acc2[i][3]);
                }
            }
        }

        // write 8-way k-split partials
#pragma unroll
        for (int i = 0; i < 8; i++) {
            float* rp = red + (kg << 11) + (bb + i) * 128 + c0;
            *reinterpret_cast<ulonglong2*>(rp)     = make_ulonglong2(acc2[i][0], acc2[i][1]);
            *reinterpret_cast<ulonglong2*>(rp + 4) = make_ulonglong2(acc2[i][2], acc2[i][3]);
        }
        __syncthreads();

        // epilogue (c in registers)
        float* ho = hist + ((size_t)t * BSZ + b0) * HIDN;
        {
            int cb = eb0 * 128 + enn0;
            float gv[4] = {xv0.x, xv0.y, xv0.z, xv0.w};
#pragma unroll
            for (int g = 0; g < 4; g++) {
                int c = cb + (g << 5);
#pragma unroll
                for (int s = 0; s < 8; s++) gv[g] += red[(s << 11) + c];
            }
            float cn = sigm(gv[1]) * creg[0] + sigm(gv[0]) * ftanh(gv[2]);
            creg[0] = cn;
            ho[(eb0 << 8) + n0 + enn0] = sigm(gv[3]) * ftanh(cn);
        }
        {
            int cb = eb1 * 128 + enn1;
            float gv[4] = {xv1.x, xv1.y, xv1.z, xv1.w};
#pragma unroll
            for (int g = 0; g < 4; g++) {
                int c = cb + (g << 5);
#pragma unroll
                for (int s = 0; s < 8; s++) gv[g] += red[(s << 11) + c];
            }
            float cn = sigm(gv[1]) * creg[1] + sigm(gv[0]) * ftanh(gv[2]);
            creg[1] = cn;
            ho[(eb1 << 8) + n0 + enn1] = sigm(gv[3]) * ftanh(cn);
        }
        __syncthreads();                               // all h stores happened-before below
        if (tid == 0) red_rel_add(g_bar + bi, 1u);     // publish step t
    }
}

// ---- head ----
__global__ void head_kernel(const float* __restrict__ Wh, const float* __restrict__ bh,
                            float* __restrict__ out)
{
    __shared__ float rs[8];
    int b = blockIdx.x, tid = threadIdx.x;
    float v = g_hist1[((size_t)(TSEQ - 1) * BSZ + b) * HIDN + tid] * Wh[tid];
#pragma unroll
    for (int o = 16; o > 0; o >>= 1) v += __shfl_down_sync(0xffffffffu, v, o);
    if ((tid & 31) == 0) rs[tid >> 5] = v;
    __syncthreads();
    if (tid < 8) {
        float s = rs[tid];
#pragma unroll
        for (int o = 4; o > 0; o >>= 1) s += __shfl_down_sync(0xffu, s, o);
        if (tid == 0) out[b] = s + bh[0];
    }
}

extern "C" void kernel_launch(void* const* d_in, const int* in_sizes, int n_in,
                              void* d_out, int out_size)
{
    const float* x      = (const float*)d_in[0];
    const float* W_ih0  = (const float*)d_in[1];
    const float* W_hh0  = (const float*)d_in[2];
    const float* b_ih0  = (const float*)d_in[3];
    const float* b_hh0  = (const float*)d_in[4];
    const float* W_ih1  = (const float*)d_in[5];
    const float* W_hh1  = (const float*)d_in[6];
    const float* b_ih1  = (const float*)d_in[7];
    const float* b_hh1  = (const float*)d_in[8];
    const float* W_head = (const float*)d_in[9];
    const float* b_head = (const float*)d_in[10];
    float* out = (float*)d_out;

    void *pxg, *ph0, *ph1;
    cudaGetSymbolAddress(&pxg, g_xg);
    cudaGetSymbolAddress(&ph0, g_hist0);
    cudaGetSymbolAddress(&ph1, g_hist1);
    float* xg = (float*)pxg; float* h0 = (float*)ph0; float* h1 = (float*)ph1;

    const int SMEM = 53312 * 4;   // 213248 B
    cudaFuncSetAttribute(rec_kernel, cudaFuncAttributeMaxDynamicSharedMemorySize, SMEM);

    dim3 gg(1024, 8);
    gemm_xg<64,  true ><<<gg, 256>>>(x,  W_ih0, b_ih0, b_hh0, xg);
    reset_bar<<<1, 32>>>();
    rec_kernel<<<128, 256, SMEM>>>(xg, W_hh0, h0);
    gemm_xg<256, false><<<gg, 256>>>(h0, W_ih1, b_ih1, b_hh1, xg);
    reset_bar<<<1, 32>>>();
    rec_kernel<<<128, 256, SMEM>>>(xg, W_hh1, h1);
    head_kernel<<<256, 256>>>(W_head, b_head, out);
}

// round 7
// speedup vs baseline: 1.4849x; 1.0376x over previous
#include <cuda_runtime.h>
#include <cstdint>

#define BSZ  256
#define TSEQ 512
#define HIDN 256

typedef unsigned long long ull;

// ---- static scratch ----
// xg layout: [t][b][n][4] (gate quads)
__device__ float g_xg[(size_t)TSEQ * BSZ * 1024];
__device__ float g_hist0[(size_t)TSEQ * BSZ * HIDN];
__device__ float g_hist1[(size_t)TSEQ * BSZ * HIDN];
__device__ unsigned g_bar[16];

__global__ void reset_bar() { if (threadIdx.x < 16) g_bar[threadIdx.x] = 0u; }

__device__ __forceinline__ float sigm(float x) { return 1.f / (1.f + __expf(-x)); }
__device__ __forceinline__ float ftanh(float x) {
    float e = __expf(-2.f * fabsf(x));
    return copysignf((1.f - e) / (1.f + e), x);
}

// ---- packed fp32x2 (Blackwell) ----
__device__ __forceinline__ ull ffma2(ull a, ull b, ull c) {
    ull d; asm("fma.rn.f32x2 %0, %1, %2, %3;" : "=l"(d) : "l"(a), "l"(b), "l"(c)); return d;
}
__device__ __forceinline__ ull add2(ull a, ull b) {
    ull d; asm("add.rn.f32x2 %0, %1, %2;" : "=l"(d) : "l"(a), "l"(b)); return d;
}
__device__ __forceinline__ ull dup2(float x) {
    ull r; asm("mov.b64 %0, {%1, %1};" : "=l"(r) : "f"(x)); return r;
}
__device__ __forceinline__ float2 unpk(ull v) {
    float2 f; asm("mov.b64 {%0, %1}, %2;" : "=f"(f.x), "=f"(f.y) : "l"(v)); return f;
}

// ---- scoped sync ----
__device__ __forceinline__ unsigned ld_acq(const unsigned* p) {
    unsigned v; asm volatile("ld.acquire.gpu.global.b32 %0, [%1];" : "=r"(v) : "l"(p)); return v;
}
__device__ __forceinline__ void red_rel_add(unsigned* p, unsigned v) {
    asm volatile("red.release.gpu.global.add.u32 [%0], %1;" :: "l"(p), "r"(v) : "memory");
}

// ---- GEMM: xg[m*256 + n] (float4 gate quad) = A_row(m).W[g*256+n] + biases ----
template<int K, bool XMODE>
__global__ void __launch_bounds__(256, 2) gemm_xg(
    const float* __restrict__ A, const float* __restrict__ W,
    const float* __restrict__ b1, const float* __restrict__ b2,
    float* __restrict__ out)
{
    __shared__ float As[16][132];
    __shared__ float Ws[16][132];   // c = g*32 + (n-n0)
    const int m0 = blockIdx.x * 128, n0 = blockIdx.y * 32;
    const int tid = threadIdx.x;
    const int tm = tid >> 4, tn = tid & 15;

    int rrv[2], kqv[2];
#pragma unroll
    for (int i = 0; i < 2; i++) { int idx = tid + (i << 8); rrv[i] = idx >> 2; kqv[i] = (idx & 3) << 2; }
    size_t aoffv[2], woffv[2];
#pragma unroll
    for (int i = 0; i < 2; i++) {
        int row = m0 + rrv[i];
        if (XMODE) aoffv[i] = ((size_t)(row & 255) * TSEQ + (row >> 8)) * K;
        else       aoffv[i] = (size_t)row * K;
        int wrow = ((rrv[i] >> 5) << 8) + n0 + (rrv[i] & 31);
        woffv[i] = (size_t)wrow * K;
    }

    ull acc[8][4];
#pragma unroll
    for (int i = 0; i < 8; i++)
#pragma unroll
        for (int j = 0; j < 4; j++) acc[i][j] = 0ull;

    float4 pa[2], pw[2];
#pragma unroll
    for (int i = 0; i < 2; i++) {
        pa[i] = *reinterpret_cast<const float4*>(A + aoffv[i] + kqv[i]);
        pw[i] = *reinterpret_cast<const float4*>(W + woffv[i] + kqv[i]);
    }

    for (int kt = 0; kt < K; kt += 16) {
#pragma unroll
        for (int i = 0; i < 2; i++) {
            int k = kqv[i], rr = rrv[i];
            As[k+0][rr]=pa[i].x; As[k+1][rr]=pa[i].y; As[k+2][rr]=pa[i].z; As[k+3][rr]=pa[i].w;
            Ws[k+0][rr]=pw[i].x; Ws[k+1][rr]=pw[i].y; Ws[k+2][rr]=pw[i].z; Ws[k+3][rr]=pw[i].w;
        }
        __syncthreads();
        if (kt + 16 < K) {
#pragma unroll
            for (int i = 0; i < 2; i++) {
                pa[i] = *reinterpret_cast<const float4*>(A + aoffv[i] + kt + 16 + kqv[i]);
                pw[i] = *reinterpret_cast<const float4*>(W + woffv[i] + kt + 16 + kqv[i]);
            }
        }
#pragma unroll
        for (int k = 0; k < 16; k++) {
            float a[8];
            *reinterpret_cast<float4*>(&a[0]) = *reinterpret_cast<const float4*>(&As[k][tm << 3]);
            *reinterpret_cast<float4*>(&a[4]) = *reinterpret_cast<const float4*>(&As[k][(tm << 3) + 4]);
            ull w2[4];
#pragma unroll
            for (int g = 0; g < 4; g++)
                w2[g] = *reinterpret_cast<const ull*>(&Ws[k][(g << 5) + (tn << 1)]);
#pragma unroll
            for (int i = 0; i < 8; i++) {
                ull ad = dup2(a[i]);
#pragma unroll
                for (int g = 0; g < 4; g++) acc[i][g] = ffma2(ad, w2[g], acc[i][g]);
            }
        }
        __syncthreads();
    }

    const int n = n0 + (tn << 1);
    float bv0[4], bv1[4];
#pragma unroll
    for (int g = 0; g < 4; g++) {
        bv0[g] = b1[(g << 8) + n]     + b2[(g << 8) + n];
        bv1[g] = b1[(g << 8) + n + 1] + b2[(g << 8) + n + 1];
    }
    float4* out4 = reinterpret_cast<float4*>(out);
#pragma unroll
    for (int i = 0; i < 8; i++) {
        int m = m0 + (tm << 3) + i;
        float2 q0 = unpk(acc[i][0]), q1 = unpk(acc[i][1]);
        float2 q2 = unpk(acc[i][2]), q3 = unpk(acc[i][3]);
        out4[(size_t)m * 256 + n]     = make_float4(q0.x+bv0[0], q1.x+bv0[1], q2.x+bv0[2], q3.x+bv0[3]);
        out4[(size_t)m * 256 + n + 1] = make_float4(q0.y+bv1[0], q1.y+bv1[1], q2.y+bv1[2], q3.y+bv1[3]);
    }
}

// ---- persistent LSTM recurrence ----
// 128 CTAs = 16 batch-groups x 8 n-groups.  Warp kg owns k-slice [32kg,32kg+32):
// private h staging (syncwarp only); gate-interleaved W and gate-quad red.
__global__ void __launch_bounds__(256, 1) rec_kernel(
    const float* __restrict__ xg, const float* __restrict__ Whh,
    float* __restrict__ hist)
{
    extern __shared__ float sm[];
    float* Wsh = sm;            // [k][nn*4+g]  32768 floats
    float* hsh = Wsh + 32768;   // 8 warps x [16][36] = 4608
    float* red = hsh + 4608;    // [kg][cell][4] = 8*16*32*4 = 16384

    const int bi = blockIdx.x >> 3, ni = blockIdx.x & 7;
    const int b0 = bi << 4, n0 = ni << 5;
    const int tid = threadIdx.x;
    const int kg  = tid >> 5;
    const int cid = tid & 31;
    const int bb  = (cid >> 4) << 3;     // 0 or 8
    const int pn  = cid & 15;            // col-pair index: cols 2pn, 2pn+1

    // Wsh[k][nn*4+g] = Whh[g*256 + n0 + nn][k]
    for (int idx = tid; idx < 8192; idx += 256) {
        int kq = idx & 63, c = idx >> 6;        // c = nn*4+g
        int nn = c >> 2, g = c & 3;
        float4 v = *reinterpret_cast<const float4*>(
            Whh + (size_t)((g << 8) + n0 + nn) * HIDN + (kq << 2));
        int k = kq << 2;
        Wsh[(k+0)*128+c]=v.x; Wsh[(k+1)*128+c]=v.y; Wsh[(k+2)*128+c]=v.z; Wsh[(k+3)*128+c]=v.w;
    }
    __syncthreads();

    // epilogue cells: p0i = 2*tid -> (eb, enn) and (eb, enn+1) (always same batch row)
    const int p0i = tid << 1;
    const int eb  = p0i >> 5, enn = p0i & 31;

    float* hshW = hsh + kg * 576;          // private [16][36]
    const float4* xg4 = reinterpret_cast<const float4*>(xg);
    float creg[2] = {0.f, 0.f};

    for (int t = 0; t < TSEQ; t++) {
        // prefetch gate quads (independent of h)
        size_t xi = ((size_t)t * BSZ + b0 + eb) * 256 + n0 + enn;
        ulonglong2 xq0 = *reinterpret_cast<const ulonglong2*>(&xg4[xi]);
        ulonglong2 xq1 = *reinterpret_cast<const ulonglong2*>(&xg4[xi + 1]);

        ull acc2[8][4];
#pragma unroll
        for (int i = 0; i < 8; i++)
#pragma unroll
            for (int j = 0; j < 4; j++) acc2[i][j] = 0ull;

        if (t > 0) {
            // warp-uniform acquire poll (orders this warp's h loads)
            const unsigned tgt = (unsigned)(t << 3);
            while (ld_acq(g_bar + bi) < tgt) {}

            // stage own k-slice: 16 batches x 32 k (4 float4 per lane)
            const float* hp = hist + ((size_t)(t - 1) * BSZ + b0) * HIDN + (kg << 5);
#pragma unroll
            for (int i = 0; i < 4; i++) {
                int f  = cid + (i << 5);       // 0..127 float4 units
                int b  = f >> 3, c4 = (f & 7) << 2;
                *reinterpret_cast<float4*>(hshW + b * 36 + c4) =
                    *reinterpret_cast<const float4*>(hp + (b << 8) + c4);
            }
            __syncwarp();

            const float* hpL = hshW + bb * 36;
            const float* wp  = Wsh + ((kg << 5) * 128) + (pn << 3);
#pragma unroll 8
            for (int k = 0; k < 32; k++) {
                ulonglong2 wa = *reinterpret_cast<const ulonglong2*>(wp);
                ulonglong2 wb = *reinterpret_cast<const ulonglong2*>(wp + 4);
                wp += 128;
#pragma unroll
                for (int i = 0; i < 8; i++) {
                    ull hd = dup2(hpL[i * 36 + k]);
                    acc2[i][0] = ffma2(hd, wa.x, acc2[i][0]);
                    acc2[i][1] = ffma2(hd, wa.y, acc2[i][1]);
                    acc2[i][2] = ffma2(hd, wb.x, acc2[i][2]);
                    acc2[i][3] = ffma2(hd, wb.y, acc2[i][3]);
                }
            }
        }

        // write gate-quad partials: red[kg][cell][4]
#pragma unroll
        for (int i = 0; i < 8; i++) {
            float* rp = red + (kg << 11) + (((bb + i) << 5) + (pn << 1)) * 4;
            *reinterpret_cast<ulonglong2*>(rp)     = make_ulonglong2(acc2[i][0], acc2[i][1]);
            *reinterpret_cast<ulonglong2*>(rp + 4) = make_ulonglong2(acc2[i][2], acc2[i][3]);
        }
        __syncthreads();

        // epilogue: packed quad reduction + activations, c in registers
        float* ho = hist + ((size_t)t * BSZ + b0 + eb) * HIDN + n0 + enn;
        float hout[2];
#pragma unroll
        for (int pp = 0; pp < 2; pp++) {
            int cell = (eb << 5) + enn + pp;
            ull s01 = pp ? xq1.x : xq0.x;
            ull s23 = pp ? xq1.y : xq0.y;
            const float* rb = red + cell * 4;
#pragma unroll
            for (int s = 0; s < 8; s++) {
                ulonglong2 r = *reinterpret_cast<const ulonglong2*>(rb + (s << 11));
                s01 = add2(s01, r.x);
                s23 = add2(s23, r.y);
            }
            float2 g01 = unpk(s01), g23 = unpk(s23);
            float cn = sigm(g01.y) * creg[pp] + sigm(g01.x) * ftanh(g23.x);
            creg[pp] = cn;
            hout[pp] = sigm(g23.y) * ftanh(cn);
        }
        *reinterpret_cast<float2*>(ho) = make_float2(hout[0], hout[1]);

        __syncthreads();                               // h stores + red reads complete
        if (tid == 0) red_rel_add(g_bar + bi, 1u);     // publish step t
    }
}

// ---- head ----
__global__ void head_kernel(const float* __restrict__ Wh, const float* __restrict__ bh,
                            float* __restrict__ out)
{
    __shared__ float rs[8];
    int b = blockIdx.x, tid = threadIdx.x;
    float v = g_hist1[((size_t)(TSEQ - 1) * BSZ + b) * HIDN + tid] * Wh[tid];
#pragma unroll
    for (int o = 16; o > 0; o >>= 1) v += __shfl_down_sync(0xffffffffu, v, o);
    if ((tid & 31) == 0) rs[tid >> 5] = v;
    __syncthreads();
    if (tid < 8) {
        float s = rs[tid];
#pragma unroll
        for (int o = 4; o > 0; o >>= 1) s += __shfl_down_sync(0xffu, s, o);
        if (tid == 0) out[b] = s + bh[0];
    }
}

extern "C" void kernel_launch(void* const* d_in, const int* in_sizes, int n_in,
                              void* d_out, int out_size)
{
    const float* x      = (const float*)d_in[0];
    const float* W_ih0  = (const float*)d_in[1];
    const float* W_hh0  = (const float*)d_in[2];
    const float* b_ih0  = (const float*)d_in[3];
    const float* b_hh0  = (const float*)d_in[4];
    const float* W_ih1  = (const float*)d_in[5];
    const float* W_hh1  = (const float*)d_in[6];
    const float* b_ih1  = (const float*)d_in[7];
    const float* b_hh1  = (const float*)d_in[8];
    const float* W_head = (const float*)d_in[9];
    const float* b_head = (const float*)d_in[10];
    float* out = (float*)d_out;

    void *pxg, *ph0, *ph1;
    cudaGetSymbolAddress(&pxg, g_xg);
    cudaGetSymbolAddress(&ph0, g_hist0);
    cudaGetSymbolAddress(&ph1, g_hist1);
    float* xg = (float*)pxg; float* h0 = (float*)ph0; float* h1 = (float*)ph1;

    const int SMEM = 53760 * 4;   // 215040 B
    cudaFuncSetAttribute(rec_kernel, cudaFuncAttributeMaxDynamicSharedMemorySize, SMEM);

    dim3 gg(1024, 8);
    gemm_xg<64,  true ><<<gg, 256>>>(x,  W_ih0, b_ih0, b_hh0, xg);
    reset_bar<<<1, 32>>>();
    rec_kernel<<<128, 256, SMEM>>>(xg, W_hh0, h0);
    gemm_xg<256, false><<<gg, 256>>>(h0, W_ih1, b_ih1, b_hh1, xg);
    reset_bar<<<1, 32>>>();
    rec_kernel<<<128, 256, SMEM>>>(xg, W_hh1, h1);
    head_kernel<<<256, 256>>>(W_head, b_head, out);
}